// round 15
// baseline (speedup 1.0000x reference)
#include <cuda_runtime.h>
#include <cuda_bf16.h>
#include <cstdint>

#define NN 50000
#define NE 400000
#define F1 192      // 64 (u_Y) + 128 (X)
#define HID 512
#define SCAN_B 256
#define NBLK ((NN + SCAN_B - 1) / SCAN_B)   // 196

// GEMM tiling (mma.sync + cp.async double buffer; static 32KB smem)
#define TM 128
#define TN 128
#define KC 16                       // K-chunk: 16 bf16 = 32 B row (SW32)
#define NCHUNK (F1 / KC)            // 12

// ---------------- scratch (device globals; no runtime allocation) ----------
// g_indeg starts zero (module init) and is RESET by k_scan3 after its last
// read each call, so the fused prolog+degree kernel may atomically increment
// it immediately. Deterministic: every call sees g_indeg == 0 on entry.
__device__ int   g_indeg[NN];
__device__ float g_dinv[NN];
__device__ int   g_rowptr[NN + 1];
__device__ int   g_fillpos[NN];
__device__ int   g_csrsrc[NE];
__device__ int   g_part[NBLK];
__device__ __nv_bfloat16 g_Ah[(size_t)NN * F1];  // bf16 hi of aggregated input
__device__ __nv_bfloat16 g_Al[(size_t)NN * F1];  // bf16 lo residual
__device__ __nv_bfloat16 g_Bh[(size_t)HID * F1]; // W1^T hi  [n][k]
__device__ __nv_bfloat16 g_Bl[(size_t)HID * F1]; // W1^T lo
__device__ float g_z2[NN * 2];                   // h1 @ W2 partials

// ---------------- PTX helpers (baseline ISA only) ---------------------------
__device__ __forceinline__ uint32_t smem_u32(const void* p) {
    return (uint32_t)__cvta_generic_to_shared(p);
}
__device__ __forceinline__ uint32_t sw32(uint32_t off) {
    return off ^ ((off >> 3) & 0x10);
}
__device__ __forceinline__ void ldm_x4(uint32_t* r, uint32_t addr) {
    asm volatile("ldmatrix.sync.aligned.m8n8.x4.shared.b16 {%0,%1,%2,%3}, [%4];"
                 : "=r"(r[0]), "=r"(r[1]), "=r"(r[2]), "=r"(r[3]) : "r"(addr));
}
__device__ __forceinline__ void mma16816(float* d, const uint32_t* a, const uint32_t* b) {
    asm volatile(
        "mma.sync.aligned.m16n8k16.row.col.f32.bf16.bf16.f32 "
        "{%0,%1,%2,%3}, {%4,%5,%6,%7}, {%8,%9}, {%0,%1,%2,%3};"
        : "+f"(d[0]), "+f"(d[1]), "+f"(d[2]), "+f"(d[3])
        : "r"(a[0]), "r"(a[1]), "r"(a[2]), "r"(a[3]), "r"(b[0]), "r"(b[1]));
}
__device__ __forceinline__ void cpa16(uint32_t dst, const void* src, int nbytes) {
    asm volatile("cp.async.cg.shared.global [%0], [%1], 16, %2;"
                 :: "r"(dst), "l"(src), "r"(nbytes));
}
__device__ __forceinline__ void cpa_commit() {
    asm volatile("cp.async.commit_group;" ::: "memory");
}
__device__ __forceinline__ void cpa_wait0() {
    asm volatile("cp.async.wait_group 0;" ::: "memory");
}

// ---------------- fused prolog + degree --------------------------------------
// i < NE           : degree histogram atomics (indeg pre-cleaned, see above)
// i < NN*2         : also zero z2
// NN*2 <= i < PN   : transpose + bf16-split W1
#define PROLOG_N (NN * 2 + HID * F1)
#define PD_N (NE > PROLOG_N ? NE : PROLOG_N)
__global__ void k_pd(const float* __restrict__ W1, const int* __restrict__ col) {
    int i = blockIdx.x * blockDim.x + threadIdx.x;
    if (i < NE) atomicAdd(&g_indeg[col[i]], 1);
    if (i < NN * 2) {
        g_z2[i] = 0.f;
    } else if (i < PROLOG_N) {
        int idx = i - NN * 2;
        int n = idx / F1, k = idx - n * F1;
        float v = W1[(size_t)k * HID + n];
        __nv_bfloat16 h = __float2bfloat16(v);
        g_Bh[idx] = h;
        g_Bl[idx] = __float2bfloat16(v - __bfloat162float(h));
    }
}

// ---------------- scan pass 1 (block sums) + dinv ----------------------------
__global__ void k_scan1() {
    __shared__ int sh[SCAN_B];
    int t = threadIdx.x;
    int i = blockIdx.x * SCAN_B + t;
    int v = (i < NN) ? g_indeg[i] : 0;
    if (i < NN) g_dinv[i] = rsqrtf((float)v + 1.0f);
    sh[t] = v;
    __syncthreads();
    #pragma unroll
    for (int off = SCAN_B / 2; off >= 1; off >>= 1) {
        if (t < off) sh[t] += sh[t + off];
        __syncthreads();
    }
    if (t == 0) g_part[blockIdx.x] = sh[0];
}

// ---------------- scan pass 2: re-scan partials + elements; self-clean -------
__global__ void k_scan3() {
    __shared__ int sh[SCAN_B];
    int t = threadIdx.x;
    int bid = blockIdx.x;
    // inclusive scan of the 196 raw partials (every block redundantly)
    int pv = (t < NBLK) ? g_part[t] : 0;
    sh[t] = pv;
    __syncthreads();
    #pragma unroll
    for (int off = 1; off < SCAN_B; off <<= 1) {
        int x = (t >= off) ? sh[t - off] : 0;
        __syncthreads();
        sh[t] += x;
        __syncthreads();
    }
    int prefix = (bid == 0) ? 0 : sh[bid - 1];
    __syncthreads();
    // element scan within this block
    int i = bid * SCAN_B + t;
    int v = (i < NN) ? g_indeg[i] : 0;
    sh[t] = v;
    __syncthreads();
    #pragma unroll
    for (int off = 1; off < SCAN_B; off <<= 1) {
        int x = (t >= off) ? sh[t - off] : 0;
        __syncthreads();
        sh[t] += x;
        __syncthreads();
    }
    int excl = sh[t] - v + prefix;
    if (i < NN) {
        g_rowptr[i] = excl;
        g_fillpos[i] = excl;
        g_indeg[i] = 0;           // self-clean for the next kernel_launch call
    }
    if (bid == 0 && t == 0) g_rowptr[NN] = NE;
}

// ---------------- CSR fill ---------------------------------------------------
__global__ void k_fill(const int* __restrict__ row, const int* __restrict__ col) {
    int e = blockIdx.x * blockDim.x + threadIdx.x;
    if (e < NE) {
        int p = atomicAdd(&g_fillpos[col[e]], 1);
        g_csrsrc[p] = row[e];
    }
}

// ---------------- layer-1 aggregation (gathers X/uY directly) + bf16 split ---
__global__ void k_agg1(const float* __restrict__ X, const float* __restrict__ uY) {
    int v = blockIdx.x;
    int j = threadIdx.x;
    float dv = g_dinv[v];
    float self = (j < 64) ? uY[v * 64 + j] : X[v * 128 + (j - 64)];
    float acc = dv * self;
    int beg = g_rowptr[v], end = g_rowptr[v + 1];
    int e = beg;
    for (; e + 1 < end; e += 2) {     // 2 independent gather chains (MLP=2)
        int u0 = g_csrsrc[e], u1 = g_csrsrc[e + 1];
        float d0 = g_dinv[u0], d1 = g_dinv[u1];
        float v0 = (j < 64) ? uY[u0 * 64 + j] : X[u0 * 128 + (j - 64)];
        float v1 = (j < 64) ? uY[u1 * 64 + j] : X[u1 * 128 + (j - 64)];
        acc += d0 * v0;
        acc += d1 * v1;
    }
    if (e < end) {
        int u = g_csrsrc[e];
        float du = g_dinv[u];
        float val = (j < 64) ? uY[u * 64 + j] : X[u * 128 + (j - 64)];
        acc += du * val;
    }
    float out = dv * acc;
    __nv_bfloat16 h = __float2bfloat16(out);
    g_Ah[(size_t)v * F1 + j] = h;
    g_Al[(size_t)v * F1 + j] = __float2bfloat16(out - __bfloat162float(h));
}

// ---------------- mma.sync GEMM, cp.async double-buffered, 1 sync/chunk ------
// D = Ah@Bh + Ah@Bl + Al@Bh (fp32 acc). CTA 128x128; 8 warps 4x2 (32x64 tiles).
// Loop order per chunk: wait(data c) -> sync -> prefetch(c+1) -> compute(c).
// The sync proves all threads finished reading buf^1 (iter c-1), so the
// prefetch into it after the sync is hazard-free; no trailing sync needed.
__global__ __launch_bounds__(256) void k_gemm(const float* __restrict__ b1,
                                              const float* __restrict__ W2) {
    __shared__ __nv_bfloat16 sAh[2][TM * KC];   // 4 KB per buffer
    __shared__ __nv_bfloat16 sAl[2][TM * KC];
    __shared__ __nv_bfloat16 sBh[2][TN * KC];
    __shared__ __nv_bfloat16 sBl[2][TN * KC];

    int tid = threadIdx.x;
    int wid = tid >> 5, lane = tid & 31;
    int wr = wid >> 1;          // 0..3  (32-row band)
    int wc = wid & 1;           // 0..1  (64-col band)
    int rowbase = blockIdx.y * TM;
    int colbase = blockIdx.x * TN;

    float acc[2][8][4];
    #pragma unroll
    for (int i = 0; i < 2; i++)
        #pragma unroll
        for (int j = 0; j < 8; j++)
            #pragma unroll
            for (int c = 0; c < 4; c++) acc[i][j][c] = 0.f;

    // loader mapping: thread -> (row m = tid>>1, 16B-half g = tid&1)
    int lm = tid >> 1, lg = tid & 1;
    int lr = rowbase + lm;
    int okA = (lr < NN) ? 16 : 0;
    uint32_t sdst = sw32((uint32_t)(lm * 32 + lg * 16));
    const char* srcAh = (const char*)&g_Ah[(size_t)lr * F1] + lg * 16;
    const char* srcAl = (const char*)&g_Al[(size_t)lr * F1] + lg * 16;
    const char* srcBh = (const char*)&g_Bh[(size_t)(colbase + lm) * F1] + lg * 16;
    const char* srcBl = (const char*)&g_Bl[(size_t)(colbase + lm) * F1] + lg * 16;

    // per-lane ldmatrix address components (32B rows)
    int a_row = wr * 32 + (lane & 15);                      // + mt*16
    int a_kb  = (lane & 16);
    int b_row = wc * 64 + (lane & 7) + ((lane & 16) >> 1);  // + p*16
    int b_kb  = (lane & 8) * 2;

    // preload chunk 0
    cpa16(smem_u32(sAh[0]) + sdst, srcAh, okA);
    cpa16(smem_u32(sAl[0]) + sdst, srcAl, okA);
    cpa16(smem_u32(sBh[0]) + sdst, srcBh, 16);
    cpa16(smem_u32(sBl[0]) + sdst, srcBl, 16);
    cpa_commit();

    #pragma unroll
    for (int c = 0; c < NCHUNK; c++) {
        int buf = c & 1;
        cpa_wait0();          // chunk c data (this thread's group) arrived
        __syncthreads();      // publish; also: everyone done reading buf^1
        if (c < NCHUNK - 1) {
            int nb = buf ^ 1;
            int koff = (c + 1) * 32;   // bytes along K
            cpa16(smem_u32(sAh[nb]) + sdst, srcAh + koff, okA);
            cpa16(smem_u32(sAl[nb]) + sdst, srcAl + koff, okA);
            cpa16(smem_u32(sBh[nb]) + sdst, srcBh + koff, 16);
            cpa16(smem_u32(sBl[nb]) + sdst, srcBl + koff, 16);
            cpa_commit();
        }

        uint32_t bAh = smem_u32(sAh[buf]), bAl = smem_u32(sAl[buf]);
        uint32_t bBh = smem_u32(sBh[buf]), bBl = smem_u32(sBl[buf]);

        uint32_t af[2][4], bh[4][4], bl[4][4];
        #pragma unroll
        for (int p = 0; p < 4; p++) {
            uint32_t off = sw32((uint32_t)((b_row + p * 16) * 32 + b_kb));
            ldm_x4(bh[p], bBh + off);
            ldm_x4(bl[p], bBl + off);
        }
        #pragma unroll
        for (int mt = 0; mt < 2; mt++) {
            uint32_t off = sw32((uint32_t)((a_row + mt * 16) * 32 + a_kb));
            ldm_x4(af[mt], bAh + off);
        }
        // term 1: Ah @ Bh ; term 2: Ah @ Bl
        #pragma unroll
        for (int mt = 0; mt < 2; mt++)
            #pragma unroll
            for (int nt = 0; nt < 8; nt++) {
                mma16816(acc[mt][nt], af[mt], &bh[nt >> 1][(nt & 1) * 2]);
                mma16816(acc[mt][nt], af[mt], &bl[nt >> 1][(nt & 1) * 2]);
            }
        // A lo fragments (reuse registers)
        #pragma unroll
        for (int mt = 0; mt < 2; mt++) {
            uint32_t off = sw32((uint32_t)((a_row + mt * 16) * 32 + a_kb));
            ldm_x4(af[mt], bAl + off);
        }
        // term 3: Al @ Bh
        #pragma unroll
        for (int mt = 0; mt < 2; mt++)
            #pragma unroll
            for (int nt = 0; nt < 8; nt++)
                mma16816(acc[mt][nt], af[mt], &bh[nt >> 1][(nt & 1) * 2]);
    }

    // ---- epilogue: bias + ReLU + W2 fold, straight from registers ----
    #pragma unroll
    for (int mt = 0; mt < 2; mt++) {
        #pragma unroll
        for (int rg = 0; rg < 2; rg++) {
            int r = rowbase + wr * 32 + mt * 16 + (lane >> 2) + rg * 8;
            float p0 = 0.f, p1 = 0.f;
            #pragma unroll
            for (int nt = 0; nt < 8; nt++) {
                #pragma unroll
                for (int q = 0; q < 2; q++) {
                    int col = colbase + wc * 64 + nt * 8 + (lane & 3) * 2 + q;
                    float v = fmaxf(acc[mt][nt][rg * 2 + q] + __ldg(&b1[col]), 0.f);
                    p0 += v * __ldg(&W2[col * 2 + 0]);
                    p1 += v * __ldg(&W2[col * 2 + 1]);
                }
            }
            p0 += __shfl_xor_sync(0xffffffffu, p0, 1);
            p1 += __shfl_xor_sync(0xffffffffu, p1, 1);
            p0 += __shfl_xor_sync(0xffffffffu, p0, 2);
            p1 += __shfl_xor_sync(0xffffffffu, p1, 2);
            if ((lane & 3) == 0 && r < NN) {
                atomicAdd(&g_z2[r * 2 + 0], p0);
                atomicAdd(&g_z2[r * 2 + 1], p1);
            }
        }
    }
}

// ---------------- layer-2 aggregation + bias + softmax -----------------------
__global__ void k_final(const float* __restrict__ b2, float* __restrict__ out) {
    int v = blockIdx.x * blockDim.x + threadIdx.x;
    if (v >= NN) return;
    float dv = g_dinv[v];
    float2 zv = *(const float2*)&g_z2[v * 2];
    float s0 = dv * zv.x;
    float s1v = dv * zv.y;
    int beg = g_rowptr[v], end = g_rowptr[v + 1];
    for (int e = beg; e < end; e++) {
        int u = g_csrsrc[e];
        float du = g_dinv[u];
        float2 zu = *(const float2*)&g_z2[u * 2];
        s0 += du * zu.x;
        s1v += du * zu.y;
    }
    float y0 = dv * s0 + b2[0];
    float y1 = dv * s1v + b2[1];
    float m = fmaxf(y0, y1);
    float e0 = __expf(y0 - m), e1 = __expf(y1 - m);
    float inv = 1.f / (e0 + e1);
    out[v * 2 + 0] = e0 * inv;
    out[v * 2 + 1] = e1 * inv;
}

// ---------------- launch ------------------------------------------------------
extern "C" void kernel_launch(void* const* d_in, const int* in_sizes, int n_in,
                              void* d_out, int out_size) {
    const int*   ei = (const int*)d_in[0];
    const float* X  = (const float*)d_in[1];
    const float* uY = (const float*)d_in[2];
    const float* W1 = (const float*)d_in[3];
    const float* b1 = (const float*)d_in[4];
    const float* W2 = (const float*)d_in[5];
    const float* b2 = (const float*)d_in[6];
    float* out = (float*)d_out;
    (void)in_sizes; (void)n_in; (void)out_size;

    const int* row = ei;        // edge_index[0] = sources
    const int* col = ei + NE;   // edge_index[1] = targets

    k_pd    <<<(PD_N + 255) / 256, 256>>>(W1, col);
    k_scan1 <<<NBLK, SCAN_B>>>();
    k_scan3 <<<NBLK, SCAN_B>>>();
    k_fill  <<<(NE + 255) / 256, 256>>>(row, col);
    k_agg1  <<<NN, F1>>>(X, uY);
    k_gemm  <<<dim3(HID / TN, (NN + TM - 1) / TM), 256>>>(b1, W2);
    k_final <<<(NN + 255) / 256, 256>>>(b2, out);
}

// round 17
// speedup vs baseline: 1.1097x; 1.1097x over previous
#include <cuda_runtime.h>
#include <cuda_bf16.h>
#include <cstdint>

#define NN 50000
#define NE 400000
#define F1 192      // 64 (u_Y) + 128 (X)
#define HID 512
#define SCAN_B 256
#define NBLK ((NN + SCAN_B - 1) / SCAN_B)   // 196

// GEMM tiling (mma.sync + cp.async double buffer; static 32KB smem)
#define TM 128
#define TN 128
#define KC 16                       // K-chunk: 16 bf16 = 32 B row (SW32)
#define NCHUNK (F1 / KC)            // 12

// ---------------- scratch (device globals; no runtime allocation) ----------
// g_indeg starts zero (module init) and is RESET by k_scan3 after its last
// read each call, so the fused prolog+degree kernel may atomically increment
// it immediately. Deterministic: every call sees g_indeg == 0 on entry.
__device__ int   g_indeg[NN];
__device__ float g_dinv[NN];
__device__ int   g_rowptr[NN + 1];
__device__ int   g_fillpos[NN];
__device__ int   g_csrsrc[NE];
__device__ int   g_part[NBLK];
__device__ __nv_bfloat16 g_Ah[(size_t)NN * F1];  // bf16 hi of aggregated input
__device__ __nv_bfloat16 g_Al[(size_t)NN * F1];  // bf16 lo residual
__device__ __nv_bfloat16 g_Bh[(size_t)HID * F1]; // W1^T hi  [n][k]
__device__ __nv_bfloat16 g_Bl[(size_t)HID * F1]; // W1^T lo
__device__ float g_z2[NN * 2];                   // h1 @ W2 partials

// ---------------- PTX helpers (baseline ISA only) ---------------------------
__device__ __forceinline__ uint32_t smem_u32(const void* p) {
    return (uint32_t)__cvta_generic_to_shared(p);
}
__device__ __forceinline__ uint32_t sw32(uint32_t off) {
    return off ^ ((off >> 3) & 0x10);
}
__device__ __forceinline__ void ldm_x4(uint32_t* r, uint32_t addr) {
    asm volatile("ldmatrix.sync.aligned.m8n8.x4.shared.b16 {%0,%1,%2,%3}, [%4];"
                 : "=r"(r[0]), "=r"(r[1]), "=r"(r[2]), "=r"(r[3]) : "r"(addr));
}
__device__ __forceinline__ void mma16816(float* d, const uint32_t* a, const uint32_t* b) {
    asm volatile(
        "mma.sync.aligned.m16n8k16.row.col.f32.bf16.bf16.f32 "
        "{%0,%1,%2,%3}, {%4,%5,%6,%7}, {%8,%9}, {%0,%1,%2,%3};"
        : "+f"(d[0]), "+f"(d[1]), "+f"(d[2]), "+f"(d[3])
        : "r"(a[0]), "r"(a[1]), "r"(a[2]), "r"(a[3]), "r"(b[0]), "r"(b[1]));
}
__device__ __forceinline__ void cpa16(uint32_t dst, const void* src, int nbytes) {
    asm volatile("cp.async.cg.shared.global [%0], [%1], 16, %2;"
                 :: "r"(dst), "l"(src), "r"(nbytes));
}
__device__ __forceinline__ void cpa_commit() {
    asm volatile("cp.async.commit_group;" ::: "memory");
}
__device__ __forceinline__ void cpa_wait1() {
    asm volatile("cp.async.wait_group 1;" ::: "memory");
}
__device__ __forceinline__ void cpa_wait0() {
    asm volatile("cp.async.wait_group 0;" ::: "memory");
}

// ---------------- fused prolog + degree --------------------------------------
// i < NE           : degree histogram atomics (indeg pre-cleaned, see above)
// i < NN*2         : also zero z2
// NN*2 <= i < PN   : transpose + bf16-split W1
#define PROLOG_N (NN * 2 + HID * F1)
#define PD_N (NE > PROLOG_N ? NE : PROLOG_N)
__global__ void k_pd(const float* __restrict__ W1, const int* __restrict__ col) {
    int i = blockIdx.x * blockDim.x + threadIdx.x;
    if (i < NE) atomicAdd(&g_indeg[col[i]], 1);
    if (i < NN * 2) {
        g_z2[i] = 0.f;
    } else if (i < PROLOG_N) {
        int idx = i - NN * 2;
        int n = idx / F1, k = idx - n * F1;
        float v = W1[(size_t)k * HID + n];
        __nv_bfloat16 h = __float2bfloat16(v);
        g_Bh[idx] = h;
        g_Bl[idx] = __float2bfloat16(v - __bfloat162float(h));
    }
}

// ---------------- scan pass 1 (block sums) + dinv ----------------------------
__global__ void k_scan1() {
    __shared__ int sh[SCAN_B];
    int t = threadIdx.x;
    int i = blockIdx.x * SCAN_B + t;
    int v = (i < NN) ? g_indeg[i] : 0;
    if (i < NN) g_dinv[i] = rsqrtf((float)v + 1.0f);
    sh[t] = v;
    __syncthreads();
    #pragma unroll
    for (int off = SCAN_B / 2; off >= 1; off >>= 1) {
        if (t < off) sh[t] += sh[t + off];
        __syncthreads();
    }
    if (t == 0) g_part[blockIdx.x] = sh[0];
}

// ---------------- scan pass 2: re-scan partials + elements; self-clean -------
__global__ void k_scan3() {
    __shared__ int sh[SCAN_B];
    int t = threadIdx.x;
    int bid = blockIdx.x;
    // inclusive scan of the 196 raw partials (every block redundantly)
    int pv = (t < NBLK) ? g_part[t] : 0;
    sh[t] = pv;
    __syncthreads();
    #pragma unroll
    for (int off = 1; off < SCAN_B; off <<= 1) {
        int x = (t >= off) ? sh[t - off] : 0;
        __syncthreads();
        sh[t] += x;
        __syncthreads();
    }
    int prefix = (bid == 0) ? 0 : sh[bid - 1];
    __syncthreads();
    // element scan within this block
    int i = bid * SCAN_B + t;
    int v = (i < NN) ? g_indeg[i] : 0;
    sh[t] = v;
    __syncthreads();
    #pragma unroll
    for (int off = 1; off < SCAN_B; off <<= 1) {
        int x = (t >= off) ? sh[t - off] : 0;
        __syncthreads();
        sh[t] += x;
        __syncthreads();
    }
    int excl = sh[t] - v + prefix;
    if (i < NN) {
        g_rowptr[i] = excl;
        g_fillpos[i] = excl;
        g_indeg[i] = 0;           // self-clean for the next kernel_launch call
    }
    if (bid == 0 && t == 0) g_rowptr[NN] = NE;
}

// ---------------- CSR fill ---------------------------------------------------
__global__ void k_fill(const int* __restrict__ row, const int* __restrict__ col) {
    int e = blockIdx.x * blockDim.x + threadIdx.x;
    if (e < NE) {
        int p = atomicAdd(&g_fillpos[col[e]], 1);
        g_csrsrc[p] = row[e];
    }
}

// ---------------- layer-1 aggregation (R13-identical hot loop) ---------------
__global__ void k_agg1(const float* __restrict__ X, const float* __restrict__ uY) {
    int v = blockIdx.x;
    int j = threadIdx.x;
    float dv = g_dinv[v];
    float self = (j < 64) ? uY[v * 64 + j] : X[v * 128 + (j - 64)];
    float acc = dv * self;
    int beg = g_rowptr[v], end = g_rowptr[v + 1];
    for (int e = beg; e < end; e++) {
        int u = g_csrsrc[e];
        float du = g_dinv[u];
        float val = (j < 64) ? uY[u * 64 + j] : X[u * 128 + (j - 64)];
        acc += du * val;
    }
    float out = dv * acc;
    __nv_bfloat16 h = __float2bfloat16(out);
    g_Ah[(size_t)v * F1 + j] = h;
    g_Al[(size_t)v * F1 + j] = __float2bfloat16(out - __bfloat162float(h));
}

// ---------------- mma.sync GEMM (R13-identical mainloop) ---------------------
// D = Ah@Bh + Ah@Bl + Al@Bh (fp32 acc). CTA 128x128; 8 warps 4x2 (32x64 tiles).
// KC=16 chunks (32B rows, SW32); 2 buffers = 32KB static.
__global__ __launch_bounds__(256) void k_gemm(const float* __restrict__ b1,
                                              const float* __restrict__ W2) {
    __shared__ __nv_bfloat16 sAh[2][TM * KC];   // 4 KB per buffer
    __shared__ __nv_bfloat16 sAl[2][TM * KC];
    __shared__ __nv_bfloat16 sBh[2][TN * KC];
    __shared__ __nv_bfloat16 sBl[2][TN * KC];

    int tid = threadIdx.x;
    int wid = tid >> 5, lane = tid & 31;
    int wr = wid >> 1;          // 0..3  (32-row band)
    int wc = wid & 1;           // 0..1  (64-col band)
    int rowbase = blockIdx.y * TM;
    int colbase = blockIdx.x * TN;

    float acc[2][8][4];
    #pragma unroll
    for (int i = 0; i < 2; i++)
        #pragma unroll
        for (int j = 0; j < 8; j++)
            #pragma unroll
            for (int c = 0; c < 4; c++) acc[i][j][c] = 0.f;

    // loader mapping: thread -> (row m = tid>>1, 16B-half g = tid&1)
    int lm = tid >> 1, lg = tid & 1;
    int lr = rowbase + lm;
    int okA = (lr < NN) ? 16 : 0;
    uint32_t sdst = sw32((uint32_t)(lm * 32 + lg * 16));
    const char* srcAh = (const char*)&g_Ah[(size_t)lr * F1] + lg * 16;
    const char* srcAl = (const char*)&g_Al[(size_t)lr * F1] + lg * 16;
    const char* srcBh = (const char*)&g_Bh[(size_t)(colbase + lm) * F1] + lg * 16;
    const char* srcBl = (const char*)&g_Bl[(size_t)(colbase + lm) * F1] + lg * 16;

    // per-lane ldmatrix address components (32B rows)
    int a_row = wr * 32 + (lane & 15);                      // + mt*16
    int a_kb  = (lane & 16);
    int b_row = wc * 64 + (lane & 7) + ((lane & 16) >> 1);  // + p*16
    int b_kb  = (lane & 8) * 2;

    // preload chunk 0
    {
        cpa16(smem_u32(sAh[0]) + sdst, srcAh, okA);
        cpa16(smem_u32(sAl[0]) + sdst, srcAl, okA);
        cpa16(smem_u32(sBh[0]) + sdst, srcBh, 16);
        cpa16(smem_u32(sBl[0]) + sdst, srcBl, 16);
        cpa_commit();
    }

    #pragma unroll
    for (int c = 0; c < NCHUNK; c++) {
        int buf = c & 1;
        if (c < NCHUNK - 1) {
            int nb = buf ^ 1;
            int koff = (c + 1) * 32;   // bytes into the K dimension
            cpa16(smem_u32(sAh[nb]) + sdst, srcAh + koff, okA);
            cpa16(smem_u32(sAl[nb]) + sdst, srcAl + koff, okA);
            cpa16(smem_u32(sBh[nb]) + sdst, srcBh + koff, 16);
            cpa16(smem_u32(sBl[nb]) + sdst, srcBl + koff, 16);
            cpa_commit();
            cpa_wait1();
        } else {
            cpa_wait0();
        }
        __syncthreads();

        uint32_t bAh = smem_u32(sAh[buf]), bAl = smem_u32(sAl[buf]);
        uint32_t bBh = smem_u32(sBh[buf]), bBl = smem_u32(sBl[buf]);

        uint32_t af[2][4], bh[4][4], bl[4][4];
        #pragma unroll
        for (int p = 0; p < 4; p++) {
            uint32_t off = sw32((uint32_t)((b_row + p * 16) * 32 + b_kb));
            ldm_x4(bh[p], bBh + off);
            ldm_x4(bl[p], bBl + off);
        }
        #pragma unroll
        for (int mt = 0; mt < 2; mt++) {
            uint32_t off = sw32((uint32_t)((a_row + mt * 16) * 32 + a_kb));
            ldm_x4(af[mt], bAh + off);
        }
        // term 1: Ah @ Bh ; term 2: Ah @ Bl
        #pragma unroll
        for (int mt = 0; mt < 2; mt++)
            #pragma unroll
            for (int nt = 0; nt < 8; nt++) {
                mma16816(acc[mt][nt], af[mt], &bh[nt >> 1][(nt & 1) * 2]);
                mma16816(acc[mt][nt], af[mt], &bl[nt >> 1][(nt & 1) * 2]);
            }
        // A lo fragments (reuse registers)
        #pragma unroll
        for (int mt = 0; mt < 2; mt++) {
            uint32_t off = sw32((uint32_t)((a_row + mt * 16) * 32 + a_kb));
            ldm_x4(af[mt], bAl + off);
        }
        // term 3: Al @ Bh
        #pragma unroll
        for (int mt = 0; mt < 2; mt++)
            #pragma unroll
            for (int nt = 0; nt < 8; nt++)
                mma16816(acc[mt][nt], af[mt], &bh[nt >> 1][(nt & 1) * 2]);
        __syncthreads();
    }

    // ---- epilogue: bias + ReLU + W2 fold, straight from registers ----
    #pragma unroll
    for (int mt = 0; mt < 2; mt++) {
        #pragma unroll
        for (int rg = 0; rg < 2; rg++) {
            int r = rowbase + wr * 32 + mt * 16 + (lane >> 2) + rg * 8;
            float p0 = 0.f, p1 = 0.f;
            #pragma unroll
            for (int nt = 0; nt < 8; nt++) {
                #pragma unroll
                for (int q = 0; q < 2; q++) {
                    int col = colbase + wc * 64 + nt * 8 + (lane & 3) * 2 + q;
                    float v = fmaxf(acc[mt][nt][rg * 2 + q] + __ldg(&b1[col]), 0.f);
                    p0 += v * __ldg(&W2[col * 2 + 0]);
                    p1 += v * __ldg(&W2[col * 2 + 1]);
                }
            }
            p0 += __shfl_xor_sync(0xffffffffu, p0, 1);
            p1 += __shfl_xor_sync(0xffffffffu, p1, 1);
            p0 += __shfl_xor_sync(0xffffffffu, p0, 2);
            p1 += __shfl_xor_sync(0xffffffffu, p1, 2);
            if ((lane & 3) == 0 && r < NN) {
                atomicAdd(&g_z2[r * 2 + 0], p0);
                atomicAdd(&g_z2[r * 2 + 1], p1);
            }
        }
    }
}

// ---------------- layer-2 aggregation + bias + softmax -----------------------
__global__ void k_final(const float* __restrict__ b2, float* __restrict__ out) {
    int v = blockIdx.x * blockDim.x + threadIdx.x;
    if (v >= NN) return;
    float dv = g_dinv[v];
    float2 zv = *(const float2*)&g_z2[v * 2];
    float s0 = dv * zv.x;
    float s1v = dv * zv.y;
    int beg = g_rowptr[v], end = g_rowptr[v + 1];
    for (int e = beg; e < end; e++) {
        int u = g_csrsrc[e];
        float du = g_dinv[u];
        float2 zu = *(const float2*)&g_z2[u * 2];
        s0 += du * zu.x;
        s1v += du * zu.y;
    }
    float y0 = dv * s0 + b2[0];
    float y1 = dv * s1v + b2[1];
    float m = fmaxf(y0, y1);
    float e0 = __expf(y0 - m), e1 = __expf(y1 - m);
    float inv = 1.f / (e0 + e1);
    out[v * 2 + 0] = e0 * inv;
    out[v * 2 + 1] = e1 * inv;
}

// ---------------- launch ------------------------------------------------------
extern "C" void kernel_launch(void* const* d_in, const int* in_sizes, int n_in,
                              void* d_out, int out_size) {
    const int*   ei = (const int*)d_in[0];
    const float* X  = (const float*)d_in[1];
    const float* uY = (const float*)d_in[2];
    const float* W1 = (const float*)d_in[3];
    const float* b1 = (const float*)d_in[4];
    const float* W2 = (const float*)d_in[5];
    const float* b2 = (const float*)d_in[6];
    float* out = (float*)d_out;
    (void)in_sizes; (void)n_in; (void)out_size;

    const int* row = ei;        // edge_index[0] = sources
    const int* col = ei + NE;   // edge_index[1] = targets

    k_pd    <<<(PD_N + 255) / 256, 256>>>(W1, col);
    k_scan1 <<<NBLK, SCAN_B>>>();
    k_scan3 <<<NBLK, SCAN_B>>>();
    k_fill  <<<(NE + 255) / 256, 256>>>(row, col);
    k_agg1  <<<NN, F1>>>(X, uY);
    k_gemm  <<<dim3(HID / TN, (NN + TM - 1) / TM), 256>>>(b1, W2);
    k_final <<<(NN + 255) / 256, 256>>>(b2, out);
}